// round 12
// baseline (speedup 1.0000x reference)
#include <cuda_runtime.h>

// Problem constants (match reference)
#define LRATE  0.001f
#define GAMMA_ 0.99f
#define LEN_C  512
#define E_     8
#define T_     2048
#define RS_    32
#define W_ELEMS 16384               // RS_ * LEN_C floats = 64KB

#define NTHR_  1024                 // threads per CTA
#define GRID_  296                  // 2 CTAs/SM x 148 SMs: all co-resident
#define PRO_   32                   // blocks in prologue phase 1

// Scratch (allocation-free rule: __device__ globals)
__device__ float    g_partial[RS_ * E_];
__device__ float    g_W[W_ELEMS];
__device__ unsigned g_bar1 = 0;     // 32-block prologue barrier
__device__ unsigned g_bar2 = 0;     // 296-block grid barrier
__device__ unsigned g_done = 0;     // completion counter -> resets all

extern __shared__ float4 sW[];      // 4096 float4 = 64KB weight tile

__device__ __forceinline__ void spin_until(unsigned* ctr, unsigned target) {
    while (*((volatile unsigned*)ctr) < target) __nanosleep(64);
}

// ---------------------------------------------------------------------------
// One fused persistent kernel — CONVERGED configuration.
// 1024 threads, 2 CTAs/SM = 64 warps/SM (architectural max): maximal MLP
// with zero extra instructions per byte. At 1024 threads the chunk mapping
// degenerates: v = it*1024 + tid, row = it*8 + (tid>>7)
//   => e = tid>>7 is a PER-THREAD CONSTANT, rs = it.
// One accumulator per thread, one atomic per warp per chunk.
//
//   Prologue: blocks 0..31 compute g_partial[row] = <Fx[row,:], W0[rs,:]>;
//             blocks 32..47 zero out[0..16383]; block 0 writes gamma.
//   32-barrier; blocks 0..15: err[e] = Dis[e,511]-sum; g_W = W0 + LR*err.Fx
//   296-barrier; all blocks: stage W->smem, barrier-free loop t = b + k*296:
//       out[t,e] += per-warp partial via atomicAdd (4 contributors/element)
// Every block prefetches its whole first 512KB chunk into L2 before the
// barriers so DRAM streams during the prologue. Measured: 6.97 TB/s
// end-to-end — at the LTS fabric cap (path-independent; TMA can't beat it).
// ---------------------------------------------------------------------------
__global__ __launch_bounds__(NTHR_, 2) void k_fused(
        const float* __restrict__ Fx,      // [RS_,E_,LEN_C]
        const float* __restrict__ Dis,     // [E_,LEN_C]
        const float* __restrict__ Fxe,     // [T_,RS_,E_,LEN_C]
        const float* __restrict__ W0,      // [RS_,LEN_C]
        float* __restrict__ out,           // [T_*E_]
        float* __restrict__ gam_out)       // [LEN_C]
{
    const int tid  = threadIdx.x;
    const int b    = blockIdx.x;
    const int wid  = tid >> 5;      // 0..31
    const int lane = tid & 31;

    __shared__ float sH[32];
    __shared__ float sErr[E_];

    // ---- static first chunk; prefetch all 512KB of it into L2 ----
    const unsigned t0 = (unsigned)b;       // < GRID_ <= T_
    {
        const char* base = (const char*)Fxe + (size_t)t0 * 524288;
        #pragma unroll
        for (int k = 0; k < 4; k++)
            asm volatile("prefetch.global.L2 [%0];"
                         :: "l"(base + (size_t)(k * 1024 + tid) * 128));
    }

    // ---- gamma vector (block 0) ----
    if (b == 0 && tid < LEN_C)
        gam_out[tid] = powf(GAMMA_, (float)(LEN_C - 1 - tid));

    // ---- zero the atomic output region (blocks 32..47, 16x1024 = 16384) ----
    if (b >= 32 && b < 48)
        out[(b - 32) * NTHR_ + tid] = 0.0f;

    // ---- prologue ----
    if (b < PRO_) {
        // Phase 1: 8 rows/block, 4 warps/row (row = rs*8+e)
        const int row = 8 * b + (wid >> 2);
        const int rs  = row >> 3;
        const int j   = (wid & 3) * 32 + lane;        // float4 index 0..127
        const float4 x = reinterpret_cast<const float4*>(Fx)[row * 128 + j];
        const float4 w = reinterpret_cast<const float4*>(W0)[rs  * 128 + j];
        float acc = x.x * w.x + x.y * w.y + x.z * w.z + x.w * w.w;
        #pragma unroll
        for (int off = 16; off > 0; off >>= 1)
            acc += __shfl_xor_sync(0xFFFFFFFFu, acc, off);
        if (lane == 0) sH[wid] = acc;
        __syncthreads();
        if (tid < 8)
            g_partial[8 * b + tid] =
                sH[4 * tid] + sH[4 * tid + 1] + sH[4 * tid + 2] + sH[4 * tid + 3];

        // 32-block barrier
        __threadfence();
        __syncthreads();
        if (tid == 0) { atomicAdd(&g_bar1, 1u); spin_until(&g_bar1, PRO_); }
        __syncthreads();
        __threadfence();

        // Phase 2 (blocks 0..15): error + weight update
        if (b < 16) {
            if (tid < E_) {
                float s = 0.0f;
                #pragma unroll
                for (int r = 0; r < RS_; r++) s += g_partial[(r << 3) | tid];
                sErr[tid] = Dis[tid * LEN_C + (LEN_C - 1)] - s;
            }
            __syncthreads();
            const int i   = b * NTHR_ + tid;           // covers [0, 16384)
            const int rs2 = i >> 9;
            const int n   = i & (LEN_C - 1);
            float s = 0.0f;
            #pragma unroll
            for (int e = 0; e < E_; e++)
                s += sErr[e] * Fx[(rs2 * E_ + e) * LEN_C + n];
            g_W[i] = W0[i] + LRATE * s;
        }
    }

    // ---- full grid barrier (all 296 resident by construction) ----
    // Also orders the out[] zeroing before any atomicAdd below.
    __threadfence();
    __syncthreads();
    if (tid == 0) { atomicAdd(&g_bar2, 1u); spin_until(&g_bar2, GRID_); }
    __syncthreads();
    __threadfence();          // acquire: g_W + zeroed out[] now visible

    // ---- stage weights into smem (4096 float4 / 1024 thr = 4 each) ----
    const float4* W4 = reinterpret_cast<const float4*>(g_W);
    #pragma unroll
    for (int i = 0; i < 4; i++) sW[tid + i * NTHR_] = W4[tid + i * NTHR_];
    __syncthreads();

    // ---- main streaming loop: static interleave, NO synchronization ----
    // Per t: v = it*1024+tid; e = tid>>7 fixed; rs = it; n4 = tid&127 fixed.
    // Lane 0 of each warp adds its warp partial to out (4 warps per (t,e)).
    const int e  = tid >> 7;          // 0..7, constant per thread
    const int n4 = tid & 127;

    for (unsigned t = t0; t < T_; t += GRID_) {
        const float4* X = reinterpret_cast<const float4*>(Fxe) + (size_t)t * 32768;

        float acc = 0.0f;

        #pragma unroll 8
        for (int it = 0; it < 32; it++) {
            const float4 x = __ldcs(&X[it * NTHR_ + tid]);
            const float4 w = sW[it * 128 + n4];
            acc += x.x * w.x + x.y * w.y + x.z * w.z + x.w * w.w;
        }

        #pragma unroll
        for (int off = 16; off > 0; off >>= 1)
            acc += __shfl_xor_sync(0xFFFFFFFFu, acc, off);
        if (lane == 0)
            atomicAdd(&out[t * E_ + e], acc);
    }

    // ---- reset counters for next graph replay (296th finisher) ----
    __syncthreads();
    if (tid == 0) {
        const unsigned v = atomicAdd(&g_done, 1u);
        if (v == GRID_ - 1) {
            g_bar1 = 0; g_bar2 = 0; g_done = 0;
            __threadfence();
        }
    }
}

// ---------------------------------------------------------------------------
extern "C" void kernel_launch(void* const* d_in, const int* in_sizes, int n_in,
                              void* d_out, int out_size) {
    const float* Fx  = (const float*)d_in[0];   // [R,S,E,LEN_C]
    const float* Dis = (const float*)d_in[1];   // [E,LEN_C]
    const float* Fxe = (const float*)d_in[2];   // [T,R,S,E,LEN_C]
    const float* W0  = (const float*)d_in[3];   // [R,S,LEN_C]
    float* out = (float*)d_out;                 // [T*E] anti_noise ++ [LEN_C] gamma

    static bool attr_set = false;
    if (!attr_set) {
        cudaFuncSetAttribute(k_fused, cudaFuncAttributeMaxDynamicSharedMemorySize, 65536);
        attr_set = true;
    }
    k_fused<<<GRID_, NTHR_, 65536>>>(Fx, Dis, Fxe, W0, out, out + (size_t)T_ * E_);
}

// round 13
// speedup vs baseline: 1.0025x; 1.0025x over previous
#include <cuda_runtime.h>

// Problem constants (match reference)
#define LRATE  0.001f
#define GAMMA_ 0.99f
#define LEN_C  512
#define E_     8
#define T_     2048
#define RS_    32
#define W_ELEMS 16384               // RS_ * LEN_C floats = 64KB

#define NTHR_  1024                 // threads per CTA
#define GRID_  296                  // 2 CTAs/SM x 148 SMs: all co-resident
#define PRO_   32                   // blocks in prologue phase 1
#define PF_K_  3                    // first-chunk prefetch: 3x128KB = 384KB/block
                                    // (296 x 384KB = 114MB < 126MB L2: fully resident)

// Scratch (allocation-free rule: __device__ globals)
__device__ float    g_partial[RS_ * E_];
__device__ float    g_W[W_ELEMS];
__device__ unsigned g_bar1 = 0;     // 32-block prologue barrier
__device__ unsigned g_bar2 = 0;     // 296-block grid barrier
__device__ unsigned g_done = 0;     // completion counter -> resets all

extern __shared__ float4 sW[];      // 4096 float4 = 64KB weight tile

__device__ __forceinline__ void spin_until(unsigned* ctr, unsigned target) {
    while (*((volatile unsigned*)ctr) < target) __nanosleep(64);
}

// ---------------------------------------------------------------------------
// One fused persistent kernel — converged configuration (R11) with the
// first-chunk prefetch trimmed from 512KB to 384KB per block so the total
// prefetch window (114MB) is fully L2-resident (was 151MB > 126MB L2,
// causing ~5MB of eviction-refetch traffic).
//
// 1024 threads, 2 CTAs/SM = 64 warps/SM (architectural max): maximal MLP
// with zero extra instructions per byte. At 1024 threads the chunk mapping
// degenerates: v = it*1024 + tid, row = it*8 + (tid>>7)
//   => e = tid>>7 is a PER-THREAD CONSTANT, rs = it.
// One accumulator per thread, one atomic per warp per chunk.
//
//   Prologue: blocks 0..31 compute g_partial[row] = <Fx[row,:], W0[rs,:]>;
//             blocks 32..47 zero out[0..16383]; block 0 writes gamma.
//   32-barrier; blocks 0..15: err[e] = Dis[e,511]-sum; g_W = W0 + LR*err.Fx
//   296-barrier; all blocks: stage W->smem, barrier-free loop t = b + k*296:
//       out[t,e] += per-warp partial via atomicAdd (4 contributors/element)
// ---------------------------------------------------------------------------
__global__ __launch_bounds__(NTHR_, 2) void k_fused(
        const float* __restrict__ Fx,      // [RS_,E_,LEN_C]
        const float* __restrict__ Dis,     // [E_,LEN_C]
        const float* __restrict__ Fxe,     // [T_,RS_,E_,LEN_C]
        const float* __restrict__ W0,      // [RS_,LEN_C]
        float* __restrict__ out,           // [T_*E_]
        float* __restrict__ gam_out)       // [LEN_C]
{
    const int tid  = threadIdx.x;
    const int b    = blockIdx.x;
    const int wid  = tid >> 5;      // 0..31
    const int lane = tid & 31;

    __shared__ float sH[32];
    __shared__ float sErr[E_];

    // ---- static first chunk; prefetch first 384KB of it into L2 ----
    const unsigned t0 = (unsigned)b;       // < GRID_ <= T_
    {
        const char* base = (const char*)Fxe + (size_t)t0 * 524288;
        #pragma unroll
        for (int k = 0; k < PF_K_; k++)
            asm volatile("prefetch.global.L2 [%0];"
                         :: "l"(base + (size_t)(k * 1024 + tid) * 128));
    }

    // ---- gamma vector (block 0) ----
    if (b == 0 && tid < LEN_C)
        gam_out[tid] = powf(GAMMA_, (float)(LEN_C - 1 - tid));

    // ---- zero the atomic output region (blocks 32..47, 16x1024 = 16384) ----
    if (b >= 32 && b < 48)
        out[(b - 32) * NTHR_ + tid] = 0.0f;

    // ---- prologue ----
    if (b < PRO_) {
        // Phase 1: 8 rows/block, 4 warps/row (row = rs*8+e)
        const int row = 8 * b + (wid >> 2);
        const int rs  = row >> 3;
        const int j   = (wid & 3) * 32 + lane;        // float4 index 0..127
        const float4 x = reinterpret_cast<const float4*>(Fx)[row * 128 + j];
        const float4 w = reinterpret_cast<const float4*>(W0)[rs  * 128 + j];
        float acc = x.x * w.x + x.y * w.y + x.z * w.z + x.w * w.w;
        #pragma unroll
        for (int off = 16; off > 0; off >>= 1)
            acc += __shfl_xor_sync(0xFFFFFFFFu, acc, off);
        if (lane == 0) sH[wid] = acc;
        __syncthreads();
        if (tid < 8)
            g_partial[8 * b + tid] =
                sH[4 * tid] + sH[4 * tid + 1] + sH[4 * tid + 2] + sH[4 * tid + 3];

        // 32-block barrier
        __threadfence();
        __syncthreads();
        if (tid == 0) { atomicAdd(&g_bar1, 1u); spin_until(&g_bar1, PRO_); }
        __syncthreads();
        __threadfence();

        // Phase 2 (blocks 0..15): error + weight update
        if (b < 16) {
            if (tid < E_) {
                float s = 0.0f;
                #pragma unroll
                for (int r = 0; r < RS_; r++) s += g_partial[(r << 3) | tid];
                sErr[tid] = Dis[tid * LEN_C + (LEN_C - 1)] - s;
            }
            __syncthreads();
            const int i   = b * NTHR_ + tid;           // covers [0, 16384)
            const int rs2 = i >> 9;
            const int n   = i & (LEN_C - 1);
            float s = 0.0f;
            #pragma unroll
            for (int e = 0; e < E_; e++)
                s += sErr[e] * Fx[(rs2 * E_ + e) * LEN_C + n];
            g_W[i] = W0[i] + LRATE * s;
        }
    }

    // ---- full grid barrier (all 296 resident by construction) ----
    // Also orders the out[] zeroing before any atomicAdd below.
    __threadfence();
    __syncthreads();
    if (tid == 0) { atomicAdd(&g_bar2, 1u); spin_until(&g_bar2, GRID_); }
    __syncthreads();
    __threadfence();          // acquire: g_W + zeroed out[] now visible

    // ---- stage weights into smem (4096 float4 / 1024 thr = 4 each) ----
    const float4* W4 = reinterpret_cast<const float4*>(g_W);
    #pragma unroll
    for (int i = 0; i < 4; i++) sW[tid + i * NTHR_] = W4[tid + i * NTHR_];
    __syncthreads();

    // ---- main streaming loop: static interleave, NO synchronization ----
    // Per t: v = it*1024+tid; e = tid>>7 fixed; rs = it; n4 = tid&127 fixed.
    // Lane 0 of each warp adds its warp partial to out (4 warps per (t,e)).
    const int e  = tid >> 7;          // 0..7, constant per thread
    const int n4 = tid & 127;

    for (unsigned t = t0; t < T_; t += GRID_) {
        const float4* X = reinterpret_cast<const float4*>(Fxe) + (size_t)t * 32768;

        float acc = 0.0f;

        #pragma unroll 8
        for (int it = 0; it < 32; it++) {
            const float4 x = __ldcs(&X[it * NTHR_ + tid]);
            const float4 w = sW[it * 128 + n4];
            acc += x.x * w.x + x.y * w.y + x.z * w.z + x.w * w.w;
        }

        #pragma unroll
        for (int off = 16; off > 0; off >>= 1)
            acc += __shfl_xor_sync(0xFFFFFFFFu, acc, off);
        if (lane == 0)
            atomicAdd(&out[t * E_ + e], acc);
    }

    // ---- reset counters for next graph replay (296th finisher) ----
    __syncthreads();
    if (tid == 0) {
        const unsigned v = atomicAdd(&g_done, 1u);
        if (v == GRID_ - 1) {
            g_bar1 = 0; g_bar2 = 0; g_done = 0;
            __threadfence();
        }
    }
}

// ---------------------------------------------------------------------------
extern "C" void kernel_launch(void* const* d_in, const int* in_sizes, int n_in,
                              void* d_out, int out_size) {
    const float* Fx  = (const float*)d_in[0];   // [R,S,E,LEN_C]
    const float* Dis = (const float*)d_in[1];   // [E,LEN_C]
    const float* Fxe = (const float*)d_in[2];   // [T,R,S,E,LEN_C]
    const float* W0  = (const float*)d_in[3];   // [R,S,LEN_C]
    float* out = (float*)d_out;                 // [T*E] anti_noise ++ [LEN_C] gamma

    static bool attr_set = false;
    if (!attr_set) {
        cudaFuncSetAttribute(k_fused, cudaFuncAttributeMaxDynamicSharedMemorySize, 65536);
        attr_set = true;
    }
    k_fused<<<GRID_, NTHR_, 65536>>>(Fx, Dis, Fxe, W0, out, out + (size_t)T_ * E_);
}